// round 2
// baseline (speedup 1.0000x reference)
#include <cuda_runtime.h>
#include <cuda_bf16.h>
#include <cstdint>
#include <cstddef>

// ---------------------------------------------------------------------------
// GlobalRouters fused pipeline (fp32 baseline)
//
//   K0 : normalize neuron_emb rows (first 1536 only), store transposed [64][1536]
//   K1 : h = x @ W^T + b              [16384 x 64]   (classic SGEMM tile)
//   K2 : per 8-token tile: logits->exp (smem), group Z, dense partials
//   K2b: deterministic reduction of 256 partials per batch -> dense [8][1536]
//   K3 : per (batch,group) top-k sparsify + renormalize + scatter to output
// ---------------------------------------------------------------------------

#define NTOK_TOTAL 16384      // B*S = 8*2048
#define DDIM       2048
#define DS         64
#define NUSE       1536       // neurons actually consumed (N_KN tail unused)
#define BATCHES    8
#define SEQ        2048
#define OUT_PER_B  1792

// K2 tiling
#define TOK        8
#define NCHUNK     128
#define EROW       1552       // padded Ebuf row (floats), 16B-multiple
#define K2_BLOCKS  (NTOK_TOTAL / TOK)          // 2048
#define K2_PERB    (K2_BLOCKS / BATCHES)       // 256 partial rows per batch
#define K2_SMEM_FLOATS (64*NCHUNK + TOK*64 + TOK*EROW + TOK + TOK*4)
#define K2_SMEM_BYTES  (K2_SMEM_FLOATS * 4)    // 84,640 B

// scratch (no allocations allowed -> device globals)
__device__ float g_h[NTOK_TOTAL * DS];                 // 4 MB
__device__ float g_embT[DS * NUSE];                    // 384 KB, [k][n]
__device__ float g_part[K2_BLOCKS * NUSE];             // 12.6 MB
__device__ float g_dense[BATCHES * NUSE];              // 48 KB

// ---------------------------------------------------------------------------
// K0: normalized + transposed embeddings. one warp per neuron row.
// ---------------------------------------------------------------------------
__global__ void __launch_bounds__(256) k0_norm(const float* __restrict__ emb) {
    int n = blockIdx.x * 8 + (threadIdx.x >> 5);
    int lane = threadIdx.x & 31;
    if (n >= NUSE) return;
    float v0 = emb[n * DS + lane];
    float v1 = emb[n * DS + 32 + lane];
    float ss = v0 * v0 + v1 * v1;
    #pragma unroll
    for (int o = 16; o; o >>= 1) ss += __shfl_xor_sync(0xFFFFFFFFu, ss, o);
    float inv = 1.0f / sqrtf(ss);
    g_embT[lane * NUSE + n]        = v0 * inv;
    g_embT[(lane + 32) * NUSE + n] = v1 * inv;
}

// ---------------------------------------------------------------------------
// K1: h[m][n] = sum_k x[m][k] * W[n][k] + b[n].  BM=64, BN=64(=DS), BK=32.
// 256 threads, 4x4 register tile each. Both smem tiles stored k-major so the
// inner loop is 2x LDS.128 + 16 FFMA.
// ---------------------------------------------------------------------------
__global__ void __launch_bounds__(256) k1_gemm(const float* __restrict__ x,
                                              const float* __restrict__ W,
                                              const float* __restrict__ bias) {
    __shared__ float As[32][64];   // [k][m]
    __shared__ float Bs[32][64];   // [k][n]
    const int tid = threadIdx.x;
    const int rowBase = blockIdx.x * 64;
    const int ty = tid >> 4;       // 0..15 -> m block
    const int tx = tid & 15;       // 0..15 -> n block
    float acc[4][4] = {};

    for (int kk = 0; kk < DDIM; kk += 32) {
        #pragma unroll
        for (int i = 0; i < 2; i++) {
            int v = tid + 256 * i;           // 0..511
            int m  = v >> 3;                 // 0..63
            int k4 = v & 7;                  // 0..7
            float4 a = *(const float4*)(x + (size_t)(rowBase + m) * DDIM + kk + k4 * 4);
            As[k4 * 4 + 0][m] = a.x; As[k4 * 4 + 1][m] = a.y;
            As[k4 * 4 + 2][m] = a.z; As[k4 * 4 + 3][m] = a.w;
            float4 w = *(const float4*)(W + (size_t)m * DDIM + kk + k4 * 4);
            Bs[k4 * 4 + 0][m] = w.x; Bs[k4 * 4 + 1][m] = w.y;
            Bs[k4 * 4 + 2][m] = w.z; Bs[k4 * 4 + 3][m] = w.w;
        }
        __syncthreads();
        #pragma unroll
        for (int k = 0; k < 32; k++) {
            float4 a = *(const float4*)(&As[k][ty * 4]);
            float4 b = *(const float4*)(&Bs[k][tx * 4]);
            acc[0][0] += a.x * b.x; acc[0][1] += a.x * b.y; acc[0][2] += a.x * b.z; acc[0][3] += a.x * b.w;
            acc[1][0] += a.y * b.x; acc[1][1] += a.y * b.y; acc[1][2] += a.y * b.z; acc[1][3] += a.y * b.w;
            acc[2][0] += a.z * b.x; acc[2][1] += a.z * b.y; acc[2][2] += a.z * b.z; acc[2][3] += a.z * b.w;
            acc[3][0] += a.w * b.x; acc[3][1] += a.w * b.y; acc[3][2] += a.w * b.z; acc[3][3] += a.w * b.w;
        }
        __syncthreads();
    }
    float4 bb = *(const float4*)(bias + tx * 4);
    #pragma unroll
    for (int i = 0; i < 4; i++) {
        float4 o = make_float4(acc[i][0] + bb.x, acc[i][1] + bb.y,
                               acc[i][2] + bb.z, acc[i][3] + bb.w);
        *(float4*)(g_h + (size_t)(rowBase + ty * 4 + i) * DS + tx * 4) = o;
    }
}

// ---------------------------------------------------------------------------
// K2: per 8-token tile. Phase 1: logits->exp into smem Ebuf (12 chunks of 128
// neurons). Phase 2: per (token,group) partition sums Z and coef = imp/Z.
// Phase 3: partial dense[n] = sum_t coef[t][g(n)] * E[t][n] -> g_part (no atomics).
// ---------------------------------------------------------------------------
__global__ void __launch_bounds__(256) k2_route(const float* __restrict__ importance) {
    extern __shared__ float sm[];
    float* esT  = sm;                          // [64][128]
    float* hs   = esT + 64 * NCHUNK;           // [TOK][64]
    float* Ebuf = hs + TOK * 64;               // [TOK][EROW]
    float* simp = Ebuf + TOK * EROW;           // [TOK]
    float* coef = simp + TOK;                  // [TOK][4]

    const int tid = threadIdx.x;
    const int bid = blockIdx.x;                // 0..2047
    const int tokBase = bid * TOK;

    // load h tile (8x64) + importance
    if (tid < TOK * 16) {
        float4 hv = ((const float4*)(g_h + (size_t)(tokBase + (tid >> 4)) * DS))[tid & 15];
        ((float4*)hs)[tid] = hv;
    }
    if (tid < TOK) simp[tid] = importance[tokBase + tid];

    const int tq = tid & 31;     // 0..31 -> 4 neurons of the 128-chunk
    const int mytok = tid >> 5;  // 0..7
    const float* hrow = hs + mytok * 64;

    for (int nc = 0; nc < NUSE / NCHUNK; nc++) {
        __syncthreads();
        // load emb^T chunk [64][128] (coalesced, no transpose needed)
        #pragma unroll
        for (int i = 0; i < 8; i++) {
            int v  = tid + 256 * i;            // 0..2047
            int k  = v >> 5;
            int c4 = v & 31;
            ((float4*)esT)[v] =
                ((const float4*)(g_embT + (size_t)k * NUSE + nc * NCHUNK))[c4];
        }
        __syncthreads();
        float4 acc = make_float4(0.f, 0.f, 0.f, 0.f);
        #pragma unroll
        for (int k = 0; k < 64; k++) {
            float hv = hrow[k];
            float4 e = ((const float4*)esT)[k * 32 + tq];
            acc.x += hv * e.x; acc.y += hv * e.y;
            acc.z += hv * e.z; acc.w += hv * e.w;
        }
        float4 ev = make_float4(__expf(acc.x), __expf(acc.y),
                                __expf(acc.z), __expf(acc.w));
        ((float4*)(Ebuf + mytok * EROW + nc * NCHUNK))[tq] = ev;
    }
    __syncthreads();

    // group partition sums -> coef
    const int gs_[4] = {0, 512, 1024, 1280};
    const int gl_[4] = {512, 512, 256, 256};
    {
        int w = tid >> 5, lane = tid & 31;
        for (int task = w; task < TOK * 4; task += 8) {
            int t = task >> 2, g = task & 3;
            float s = 0.f;
            const float* row = Ebuf + t * EROW + gs_[g];
            for (int i = lane; i < gl_[g]; i += 32) s += row[i];
            #pragma unroll
            for (int o = 16; o; o >>= 1) s += __shfl_xor_sync(0xFFFFFFFFu, s, o);
            if (lane == 0) coef[t * 4 + g] = simp[t] / s;
        }
    }
    __syncthreads();

    // dense partial over this tile's 8 tokens
    float* part = g_part + (size_t)bid * NUSE;
    for (int n = tid; n < NUSE; n += 256) {
        int g = (n < 512) ? 0 : (n < 1024) ? 1 : (n < 1280) ? 2 : 3;
        float s = 0.f;
        #pragma unroll
        for (int t = 0; t < TOK; t++) s += coef[t * 4 + g] * Ebuf[t * EROW + n];
        part[n] = s;
    }
}

// ---------------------------------------------------------------------------
// K2b: deterministic reduction of the 256 per-tile partials of each batch.
// ---------------------------------------------------------------------------
__global__ void __launch_bounds__(256) k2b_reduce() {
    int gidx = blockIdx.x * 256 + threadIdx.x;           // < 8*1536
    if (gidx >= BATCHES * NUSE) return;
    int b = gidx / NUSE, n = gidx - b * NUSE;
    const float* p = g_part + (size_t)b * K2_PERB * NUSE + n;
    float s = 0.f;
    for (int j = 0; j < K2_PERB; j++) s += p[(size_t)j * NUSE];
    g_dense[b * NUSE + n] = s;
}

// ---------------------------------------------------------------------------
// K3: per (batch,group) top-k sparsify + renormalize. Writes the full output
// slice (d_out is poisoned). Group 2 (relational) is duplicated into rk slot.
// ---------------------------------------------------------------------------
__global__ void __launch_bounds__(256) k3_topk(float* __restrict__ out) {
    const int gs_[4]  = {0, 512, 1024, 1280};
    const int gl_[4]  = {512, 512, 256, 256};
    const int kk_[4]  = {8, 8, 4, 6};
    const int oo_[4]  = {0, 512, 1024, 1536};

    int task = blockIdx.x;          // 0..31
    int b = task >> 2, g = task & 3;
    int len = gl_[g], K = kk_[g];

    __shared__ float sv[512];
    __shared__ float wv[512];
    __shared__ unsigned char sel[512];
    __shared__ float red[8];
    __shared__ int   redi[8];
    __shared__ float s_ksum;

    const float* dn = g_dense + b * NUSE + gs_[g];
    for (int i = threadIdx.x; i < len; i += 256) {
        float v = dn[i];
        sv[i] = v; wv[i] = v; sel[i] = 0;
    }
    if (threadIdx.x == 0) s_ksum = 0.f;
    __syncthreads();

    for (int it = 0; it < K; it++) {
        float best = -1e30f; int bi = 0x7FFFFFFF;
        for (int i = threadIdx.x; i < len; i += 256) {
            float v = wv[i];
            if (v > best || (v == best && i < bi)) { best = v; bi = i; }
        }
        #pragma unroll
        for (int o = 16; o; o >>= 1) {
            float ov = __shfl_xor_sync(0xFFFFFFFFu, best, o);
            int   oi = __shfl_xor_sync(0xFFFFFFFFu, bi,   o);
            if (ov > best || (ov == best && oi < bi)) { best = ov; bi = oi; }
        }
        if ((threadIdx.x & 31) == 0) { red[threadIdx.x >> 5] = best; redi[threadIdx.x >> 5] = bi; }
        __syncthreads();
        if (threadIdx.x == 0) {
            float bb = red[0]; int bbi = redi[0];
            for (int w = 1; w < 8; w++)
                if (red[w] > bb || (red[w] == bb && redi[w] < bbi)) { bb = red[w]; bbi = redi[w]; }
            sel[bbi] = 1; wv[bbi] = -1e30f; s_ksum += sv[bbi];
        }
        __syncthreads();
    }

    float inv = 1.0f / (s_ksum + 1e-8f);
    float* ob = out + b * OUT_PER_B;
    for (int i = threadIdx.x; i < len; i += 256) {
        float o = sel[i] ? sv[i] * inv : 0.0f;
        ob[oo_[g] + i] = o;
        if (g == 2) ob[1280 + i] = o;   // rk_w == rq_w
    }
}

// ---------------------------------------------------------------------------
extern "C" void kernel_launch(void* const* d_in, const int* in_sizes, int n_in,
                              void* d_out, int out_size) {
    const float* x    = (const float*)d_in[0];
    const float* imp  = (const float*)d_in[1];
    const float* W    = (const float*)d_in[2];
    const float* bias = (const float*)d_in[3];
    const float* emb  = (const float*)d_in[4];
    float* out = (float*)d_out;
    (void)in_sizes; (void)n_in; (void)out_size;

    (void)cudaFuncSetAttribute(k2_route, cudaFuncAttributeMaxDynamicSharedMemorySize,
                               K2_SMEM_BYTES);

    k0_norm<<<(NUSE + 7) / 8, 256>>>(emb);
    k1_gemm<<<NTOK_TOTAL / 64, 256>>>(x, W, bias);
    k2_route<<<K2_BLOCKS, 256, K2_SMEM_BYTES>>>(imp);
    k2b_reduce<<<(BATCHES * NUSE + 255) / 256, 256>>>();
    k3_topk<<<BATCHES * 4, 256>>>(out);
}

// round 6
// speedup vs baseline: 3.4930x; 3.4930x over previous
#include <cuda_runtime.h>
#include <cuda_bf16.h>
#include <cstdint>
#include <cstddef>

// ---------------------------------------------------------------------------
// GlobalRouters, round 6: both GEMMs on mma.sync.m16n8k16 bf16 (split hi/lo).
// Target is plain sm_100 (no 'a' suffix) -> no tcgen05; ldmatrix+mma.sync only.
//
//   K0 : normalize emb rows (1536 used), split bf16 hi/lo, [n][64]
//   K0w: split W to bf16 hi/lo, [64][2048]
//   K1 : h = x@W^T + b via mma.sync (3-term split), emits h hi/lo bf16 [m][64]
//   K2 : 64 tokens/CTA, group-at-a-time: logits (mma) -> exp -> Z -> dense part
//   K2b: reduce 32 partials per batch -> dense [8][1536]
//   K3 : per (batch,group) top-k + renormalize + scatter
// ---------------------------------------------------------------------------

#define NTOK_TOTAL 16384
#define DDIM       2048
#define DS         64
#define NUSE       1536
#define BATCHES    8
#define OUT_PER_B  1792

// K2 geometry
#define K2_TOK     64
#define K2_BLOCKS  (NTOK_TOTAL / K2_TOK)      // 256
#define BLK_PER_B  (K2_BLOCKS / BATCHES)      // 32
#define EPITCH     513                        // Ebuf row pitch (floats)

// K2 dynamic smem layout (bytes)
#define OFF_AH     0                          // 64 x 128B
#define OFF_AL     8192
#define OFF_BH     16384                      // 256 x 128B
#define OFF_BL     49152
#define OFF_E      81920                      // 64 x 513 x 4 = 131328
#define OFF_Z      213248                     // 64 x 2 floats
#define OFF_COEF   213760                     // 64 floats
#define K2_SMEM    214016

// swizzled smem offset for (row, byteInRow) with 128B rows
#define SWZ(r, b)  (((unsigned)(r) << 7) + ((unsigned)(b) ^ ((((unsigned)(r)) & 7u) << 4)))

// scratch
__device__ __nv_bfloat16 g_embB_hi[NUSE * DS];
__device__ __nv_bfloat16 g_embB_lo[NUSE * DS];
__device__ __nv_bfloat16 g_WB_hi[DS * DDIM];
__device__ __nv_bfloat16 g_WB_lo[DS * DDIM];
__device__ __nv_bfloat16 g_hB_hi[NTOK_TOTAL * DS];
__device__ __nv_bfloat16 g_hB_lo[NTOK_TOTAL * DS];
__device__ float g_part[K2_BLOCKS * NUSE];
__device__ float g_dense[BATCHES * NUSE];

// ---- helpers --------------------------------------------------------------
__device__ __forceinline__ uint32_t smem_u32(const void* p) {
    uint32_t a;
    asm("{ .reg .u64 t; cvta.to.shared.u64 t, %1; cvt.u32.u64 %0, t; }"
        : "=r"(a) : "l"(p));
    return a;
}

__device__ __forceinline__ void ldsm4(uint32_t& r0, uint32_t& r1,
                                      uint32_t& r2, uint32_t& r3, uint32_t a) {
    asm volatile("ldmatrix.sync.aligned.m8n8.x4.shared.b16 {%0,%1,%2,%3}, [%4];"
                 : "=r"(r0), "=r"(r1), "=r"(r2), "=r"(r3) : "r"(a));
}

__device__ __forceinline__ void mma16816(float* d, const uint32_t* a,
                                         uint32_t b0, uint32_t b1) {
    asm volatile("mma.sync.aligned.m16n8k16.row.col.f32.bf16.bf16.f32 "
                 "{%0,%1,%2,%3}, {%4,%5,%6,%7}, {%8,%9}, {%0,%1,%2,%3};"
                 : "+f"(d[0]), "+f"(d[1]), "+f"(d[2]), "+f"(d[3])
                 : "r"(a[0]), "r"(a[1]), "r"(a[2]), "r"(a[3]), "r"(b0), "r"(b1));
}

__device__ __forceinline__ uint32_t bits2(__nv_bfloat162 v) {
    return *reinterpret_cast<uint32_t*>(&v);
}

// ---------------------------------------------------------------------------
// K0: normalize emb + bf16 split, [n][64]
// ---------------------------------------------------------------------------
__global__ void __launch_bounds__(256) k0_norm(const float* __restrict__ emb) {
    int n = blockIdx.x * 8 + (threadIdx.x >> 5);
    int lane = threadIdx.x & 31;
    if (n >= NUSE) return;
    float v0 = emb[n * DS + lane];
    float v1 = emb[n * DS + 32 + lane];
    float ss = v0 * v0 + v1 * v1;
    #pragma unroll
    for (int o = 16; o; o >>= 1) ss += __shfl_xor_sync(0xFFFFFFFFu, ss, o);
    float inv = 1.0f / sqrtf(ss);
    v0 *= inv; v1 *= inv;
    __nv_bfloat16 h0 = __float2bfloat16(v0);
    __nv_bfloat16 h1 = __float2bfloat16(v1);
    g_embB_hi[n * DS + lane]      = h0;
    g_embB_hi[n * DS + 32 + lane] = h1;
    g_embB_lo[n * DS + lane]      = __float2bfloat16(v0 - __bfloat162float(h0));
    g_embB_lo[n * DS + 32 + lane] = __float2bfloat16(v1 - __bfloat162float(h1));
}

// ---------------------------------------------------------------------------
// K0w: split W
// ---------------------------------------------------------------------------
__global__ void __launch_bounds__(256) k0_w(const float* __restrict__ W) {
    int i = blockIdx.x * 256 + threadIdx.x;
    if (i >= DS * DDIM) return;
    float v = W[i];
    __nv_bfloat16 h = __float2bfloat16(v);
    g_WB_hi[i] = h;
    g_WB_lo[i] = __float2bfloat16(v - __bfloat162float(h));
}

// ---------------------------------------------------------------------------
// K1: h = x @ W^T + b via mma.sync, 64-token CTAs, BK=64, reg-prefetch pipeline
// ---------------------------------------------------------------------------
__global__ void __launch_bounds__(256) k1_mma(const float* __restrict__ x,
                                             const float* __restrict__ bias) {
    __shared__ __align__(16) char xh[8192];
    __shared__ __align__(16) char xl[8192];
    __shared__ __align__(16) char wh[8192];
    __shared__ __align__(16) char wl[8192];
    __shared__ float sbias[64];

    const int tid = threadIdx.x;
    const int lane = tid & 31;
    const int w = tid >> 5;
    const int wtok = w >> 1;       // 0..3
    const int nhalf = w & 1;       // 0..1
    const int rowBase = blockIdx.x * 64;

    const uint32_t xhB = smem_u32(xh), xlB = smem_u32(xl);
    const uint32_t whB = smem_u32(wh), wlB = smem_u32(wl);

    if (tid < 16) ((float4*)sbias)[tid] = ((const float4*)bias)[tid];

    float acc[4][4] = {};
    float4 xv[4];
    uint4  wvh[2], wvl[2];

    // prefetch chunk 0
    {
        #pragma unroll
        for (int i = 0; i < 4; i++) {
            int f = tid + i * 256;
            int row = f >> 4, kq = f & 15;
            xv[i] = *(const float4*)(x + (size_t)(rowBase + row) * DDIM + kq * 4);
        }
        #pragma unroll
        for (int i = 0; i < 2; i++) {
            int u = tid + i * 256;
            int row = u >> 3, kq8 = u & 7;
            wvh[i] = *(const uint4*)(g_WB_hi + (size_t)row * DDIM + kq8 * 8);
            wvl[i] = *(const uint4*)(g_WB_lo + (size_t)row * DDIM + kq8 * 8);
        }
    }

    for (int c = 0; c < DDIM / 64; c++) {
        if (c) __syncthreads();
        // store stage: convert x to hi/lo bf16, store swizzled
        #pragma unroll
        for (int i = 0; i < 4; i++) {
            int f = tid + i * 256;
            int row = f >> 4, kq = f & 15;
            float4 v = xv[i];
            __nv_bfloat162 h0 = __floats2bfloat162_rn(v.x, v.y);
            __nv_bfloat162 h1 = __floats2bfloat162_rn(v.z, v.w);
            __nv_bfloat162 l0 = __floats2bfloat162_rn(v.x - __bfloat162float(h0.x),
                                                      v.y - __bfloat162float(h0.y));
            __nv_bfloat162 l1 = __floats2bfloat162_rn(v.z - __bfloat162float(h1.x),
                                                      v.w - __bfloat162float(h1.y));
            uint32_t off = SWZ(row, kq * 8);
            *(uint2*)(xh + off) = make_uint2(bits2(h0), bits2(h1));
            *(uint2*)(xl + off) = make_uint2(bits2(l0), bits2(l1));
        }
        #pragma unroll
        for (int i = 0; i < 2; i++) {
            int u = tid + i * 256;
            int row = u >> 3, kq8 = u & 7;
            uint32_t off = SWZ(row, kq8 * 16);
            *(uint4*)(wh + off) = wvh[i];
            *(uint4*)(wl + off) = wvl[i];
        }
        __syncthreads();

        // prefetch next chunk
        if (c + 1 < DDIM / 64) {
            int kk = (c + 1) * 64;
            #pragma unroll
            for (int i = 0; i < 4; i++) {
                int f = tid + i * 256;
                int row = f >> 4, kq = f & 15;
                xv[i] = *(const float4*)(x + (size_t)(rowBase + row) * DDIM + kk + kq * 4);
            }
            #pragma unroll
            for (int i = 0; i < 2; i++) {
                int u = tid + i * 256;
                int row = u >> 3, kq8 = u & 7;
                wvh[i] = *(const uint4*)(g_WB_hi + (size_t)row * DDIM + kk + kq8 * 8);
                wvl[i] = *(const uint4*)(g_WB_lo + (size_t)row * DDIM + kk + kq8 * 8);
            }
        }

        // compute: 4 ksteps of 16
        #pragma unroll
        for (int ks = 0; ks < 4; ks++) {
            uint32_t ah[4], al[4];
            {
                int R = wtok * 16 + (lane & 15);
                int byte = ks * 32 + (lane >> 4) * 16;
                ldsm4(ah[0], ah[1], ah[2], ah[3], xhB + SWZ(R, byte));
                ldsm4(al[0], al[1], al[2], al[3], xlB + SWZ(R, byte));
            }
            #pragma unroll
            for (int p = 0; p < 2; p++) {
                int R = nhalf * 32 + (2 * p + (lane >= 16 ? 1 : 0)) * 8 + (lane & 7);
                int byte = ks * 32 + ((lane >> 3) & 1) * 16;
                uint32_t bh0, bh1, bh2, bh3, bl0, bl1, bl2, bl3;
                ldsm4(bh0, bh1, bh2, bh3, whB + SWZ(R, byte));
                ldsm4(bl0, bl1, bl2, bl3, wlB + SWZ(R, byte));
                mma16816(acc[2 * p],     ah, bh0, bh1);
                mma16816(acc[2 * p],     ah, bl0, bl1);
                mma16816(acc[2 * p],     al, bh0, bh1);
                mma16816(acc[2 * p + 1], ah, bh2, bh3);
                mma16816(acc[2 * p + 1], ah, bl2, bl3);
                mma16816(acc[2 * p + 1], al, bh2, bh3);
            }
        }
    }

    // epilogue: + bias, split to bf16 hi/lo, store [m][64]
    #pragma unroll
    for (int n8 = 0; n8 < 4; n8++) {
        int n = nhalf * 32 + n8 * 8 + 2 * (lane & 3);
        int r0 = rowBase + wtok * 16 + (lane >> 2);
        int r1 = r0 + 8;
        float b0 = sbias[n], b1 = sbias[n + 1];
        float v00 = acc[n8][0] + b0, v01 = acc[n8][1] + b1;
        float v10 = acc[n8][2] + b0, v11 = acc[n8][3] + b1;
        __nv_bfloat162 h0 = __floats2bfloat162_rn(v00, v01);
        __nv_bfloat162 h1 = __floats2bfloat162_rn(v10, v11);
        __nv_bfloat162 l0 = __floats2bfloat162_rn(v00 - __bfloat162float(h0.x),
                                                  v01 - __bfloat162float(h0.y));
        __nv_bfloat162 l1 = __floats2bfloat162_rn(v10 - __bfloat162float(h1.x),
                                                  v11 - __bfloat162float(h1.y));
        *(__nv_bfloat162*)(g_hB_hi + (size_t)r0 * DS + n) = h0;
        *(__nv_bfloat162*)(g_hB_hi + (size_t)r1 * DS + n) = h1;
        *(__nv_bfloat162*)(g_hB_lo + (size_t)r0 * DS + n) = l0;
        *(__nv_bfloat162*)(g_hB_lo + (size_t)r1 * DS + n) = l1;
    }
}

// ---------------------------------------------------------------------------
// K2: 64 tokens/CTA. For each group: chunks of 256 neurons -> mma logits ->
// exp into Ebuf + Z partials; then coef=imp/Z and column-reduce -> g_part.
// ---------------------------------------------------------------------------
__global__ void __launch_bounds__(256) k2_route(const float* __restrict__ importance) {
    extern __shared__ __align__(16) char sm[];
    const uint32_t base = smem_u32(sm);
    float* Ebuf = (float*)(sm + OFF_E);
    float* zsm  = (float*)(sm + OFF_Z);
    float* coef = (float*)(sm + OFF_COEF);

    const int tid = threadIdx.x;
    const int lane = tid & 31;
    const int w = tid >> 5;
    const int wtok = w >> 1;      // 0..3
    const int nhalf = w & 1;      // 0..1
    const int bid = blockIdx.x;
    const int tokBase = bid * K2_TOK;

    // A tiles (h hi/lo): 64 rows x 128B, swizzled
    #pragma unroll
    for (int i = 0; i < 2; i++) {
        int u = tid + i * 256;
        int row = u >> 3, kq8 = u & 7;
        uint32_t off = SWZ(row, kq8 * 16);
        *(uint4*)(sm + OFF_AH + off) =
            *(const uint4*)(g_hB_hi + (size_t)(tokBase + row) * DS + kq8 * 8);
        *(uint4*)(sm + OFF_AL + off) =
            *(const uint4*)(g_hB_lo + (size_t)(tokBase + row) * DS + kq8 * 8);
    }
    if (tid < 128) zsm[tid] = 0.f;

    const int gstart[4]  = {0, 2, 4, 5};   // first chunk of group
    const int gnch[4]    = {2, 2, 1, 1};   // chunks per group
    const int gbase[4]   = {0, 512, 1024, 1280};
    const int gwidth[4]  = {512, 512, 256, 256};

    for (int grp = 0; grp < 4; grp++) {
        for (int ci = 0; ci < gnch[grp]; ci++) {
            const int chunk = gstart[grp] + ci;
            const int nb = chunk * 256;
            __syncthreads();
            // B tiles (emb hi/lo): 256 rows x 128B
            #pragma unroll
            for (int i = 0; i < 8; i++) {
                int u = tid + i * 256;
                int row = u >> 3, kq8 = u & 7;
                uint32_t off = SWZ(row, kq8 * 16);
                *(uint4*)(sm + OFF_BH + off) =
                    *(const uint4*)(g_embB_hi + (size_t)(nb + row) * DS + kq8 * 8);
                *(uint4*)(sm + OFF_BL + off) =
                    *(const uint4*)(g_embB_lo + (size_t)(nb + row) * DS + kq8 * 8);
            }
            __syncthreads();

            float acc[16][4];
            #pragma unroll
            for (int i = 0; i < 16; i++) {
                acc[i][0] = 0.f; acc[i][1] = 0.f; acc[i][2] = 0.f; acc[i][3] = 0.f;
            }
            #pragma unroll
            for (int ks = 0; ks < 4; ks++) {
                uint32_t ah[4], al[4];
                {
                    int R = wtok * 16 + (lane & 15);
                    int byte = ks * 32 + (lane >> 4) * 16;
                    ldsm4(ah[0], ah[1], ah[2], ah[3], base + OFF_AH + SWZ(R, byte));
                    ldsm4(al[0], al[1], al[2], al[3], base + OFF_AL + SWZ(R, byte));
                }
                #pragma unroll
                for (int p = 0; p < 8; p++) {
                    int R = nhalf * 128 + (2 * p + (lane >= 16 ? 1 : 0)) * 8 + (lane & 7);
                    int byte = ks * 32 + ((lane >> 3) & 1) * 16;
                    uint32_t bh0, bh1, bh2, bh3, bl0, bl1, bl2, bl3;
                    ldsm4(bh0, bh1, bh2, bh3, base + OFF_BH + SWZ(R, byte));
                    ldsm4(bl0, bl1, bl2, bl3, base + OFF_BL + SWZ(R, byte));
                    mma16816(acc[2 * p],     ah, bh0, bh1);
                    mma16816(acc[2 * p],     ah, bl0, bl1);
                    mma16816(acc[2 * p],     al, bh0, bh1);
                    mma16816(acc[2 * p + 1], ah, bh2, bh3);
                    mma16816(acc[2 * p + 1], ah, bl2, bl3);
                    mma16816(acc[2 * p + 1], al, bh2, bh3);
                }
            }

            // exp -> Ebuf, Z partials
            const int r0 = wtok * 16 + (lane >> 2);
            const int r1 = r0 + 8;
            float z0 = 0.f, z1 = 0.f;
            #pragma unroll
            for (int n8 = 0; n8 < 16; n8++) {
                int colg = ci * 256 + nhalf * 128 + n8 * 8 + 2 * (lane & 3);
                float e00 = __expf(acc[n8][0]);
                float e01 = __expf(acc[n8][1]);
                float e10 = __expf(acc[n8][2]);
                float e11 = __expf(acc[n8][3]);
                Ebuf[r0 * EPITCH + colg]     = e00;
                Ebuf[r0 * EPITCH + colg + 1] = e01;
                Ebuf[r1 * EPITCH + colg]     = e10;
                Ebuf[r1 * EPITCH + colg + 1] = e11;
                z0 += e00 + e01;
                z1 += e10 + e11;
            }
            z0 += __shfl_xor_sync(0xFFFFFFFFu, z0, 1);
            z0 += __shfl_xor_sync(0xFFFFFFFFu, z0, 2);
            z1 += __shfl_xor_sync(0xFFFFFFFFu, z1, 1);
            z1 += __shfl_xor_sync(0xFFFFFFFFu, z1, 2);
            if ((lane & 3) == 0) {
                zsm[r0 * 2 + nhalf] += z0;
                zsm[r1 * 2 + nhalf] += z1;
            }
        }
        __syncthreads();
        if (tid < K2_TOK) {
            float Z = zsm[tid * 2] + zsm[tid * 2 + 1];
            coef[tid] = importance[tokBase + tid] / Z;
            zsm[tid * 2] = 0.f;
            zsm[tid * 2 + 1] = 0.f;
        }
        __syncthreads();
        // column reduce: dense partial over 64 tokens
        for (int n = tid; n < gwidth[grp]; n += 256) {
            float s = 0.f;
            #pragma unroll 8
            for (int t = 0; t < K2_TOK; t++)
                s += coef[t] * Ebuf[t * EPITCH + n];
            g_part[(size_t)bid * NUSE + gbase[grp] + n] = s;
        }
    }
}

// ---------------------------------------------------------------------------
// K2b: reduce 32 per-tile partials per batch
// ---------------------------------------------------------------------------
__global__ void __launch_bounds__(256) k2b_reduce() {
    int gidx = blockIdx.x * 256 + threadIdx.x;
    if (gidx >= BATCHES * NUSE) return;
    int b = gidx / NUSE, n = gidx - b * NUSE;
    const float* p = g_part + (size_t)b * BLK_PER_B * NUSE + n;
    float sum = 0.f;
    #pragma unroll
    for (int j = 0; j < BLK_PER_B; j++) sum += p[(size_t)j * NUSE];
    g_dense[b * NUSE + n] = sum;
}

// ---------------------------------------------------------------------------
// K3: per (batch,group) top-k + renormalize + scatter (rq duplicated into rk)
// ---------------------------------------------------------------------------
__global__ void __launch_bounds__(256) k3_topk(float* __restrict__ out) {
    const int gs_[4]  = {0, 512, 1024, 1280};
    const int gl_[4]  = {512, 512, 256, 256};
    const int kk_[4]  = {8, 8, 4, 6};
    const int oo_[4]  = {0, 512, 1024, 1536};

    int task = blockIdx.x;
    int b = task >> 2, g = task & 3;
    int len = gl_[g], K = kk_[g];

    __shared__ float sv[512];
    __shared__ float wv[512];
    __shared__ unsigned char sel[512];
    __shared__ float red[8];
    __shared__ int   redi[8];
    __shared__ float s_ksum;

    const float* dn = g_dense + b * NUSE + gs_[g];
    for (int i = threadIdx.x; i < len; i += 256) {
        float v = dn[i];
        sv[i] = v; wv[i] = v; sel[i] = 0;
    }
    if (threadIdx.x == 0) s_ksum = 0.f;
    __syncthreads();

    for (int it = 0; it < K; it++) {
        float best = -1e30f; int bi = 0x7FFFFFFF;
        for (int i = threadIdx.x; i < len; i += 256) {
            float v = wv[i];
            if (v > best || (v == best && i < bi)) { best = v; bi = i; }
        }
        #pragma unroll
        for (int o = 16; o; o >>= 1) {
            float ov = __shfl_xor_sync(0xFFFFFFFFu, best, o);
            int   oi = __shfl_xor_sync(0xFFFFFFFFu, bi,   o);
            if (ov > best || (ov == best && oi < bi)) { best = ov; bi = oi; }
        }
        if ((threadIdx.x & 31) == 0) { red[threadIdx.x >> 5] = best; redi[threadIdx.x >> 5] = bi; }
        __syncthreads();
        if (threadIdx.x == 0) {
            float bb = red[0]; int bbi = redi[0];
            for (int ww = 1; ww < 8; ww++)
                if (red[ww] > bb || (red[ww] == bb && redi[ww] < bbi)) { bb = red[ww]; bbi = redi[ww]; }
            sel[bbi] = 1; wv[bbi] = -1e30f; s_ksum += sv[bbi];
        }
        __syncthreads();
    }

    float inv = 1.0f / (s_ksum + 1e-8f);
    float* ob = out + b * OUT_PER_B;
    for (int i = threadIdx.x; i < len; i += 256) {
        float o = sel[i] ? sv[i] * inv : 0.0f;
        ob[oo_[g] + i] = o;
        if (g == 2) ob[1280 + i] = o;
    }
}

// ---------------------------------------------------------------------------
extern "C" void kernel_launch(void* const* d_in, const int* in_sizes, int n_in,
                              void* d_out, int out_size) {
    const float* x    = (const float*)d_in[0];
    const float* imp  = (const float*)d_in[1];
    const float* W    = (const float*)d_in[2];
    const float* bias = (const float*)d_in[3];
    const float* emb  = (const float*)d_in[4];
    float* out = (float*)d_out;
    (void)in_sizes; (void)n_in; (void)out_size;

    (void)cudaFuncSetAttribute(k2_route, cudaFuncAttributeMaxDynamicSharedMemorySize,
                               K2_SMEM);

    k0_norm<<<NUSE / 8, 256>>>(emb);
    k0_w<<<(DS * DDIM) / 256, 256>>>(W);
    k1_mma<<<NTOK_TOTAL / 64, 256>>>(x, bias);
    k2_route<<<K2_BLOCKS, 256, K2_SMEM>>>(imp);
    k2b_reduce<<<(BATCHES * NUSE + 255) / 256, 256>>>();
    k3_topk<<<BATCHES * 4, 256>>>(out);
}

// round 9
// speedup vs baseline: 3.7594x; 1.0763x over previous
#include <cuda_runtime.h>
#include <cuda_bf16.h>
#include <cstdint>
#include <cstddef>

// ---------------------------------------------------------------------------
// GlobalRouters, round 9: round-8 pipeline with fp32 Ebuf (bf16 Ebuf noise
// 1.6e-5 flipped top-k ranks; measured gap bound (1e-7, 1.6e-5) demands fp32).
// ---------------------------------------------------------------------------

#define NTOK_TOTAL 16384
#define DDIM       2048
#define DS         64
#define NUSE       1536
#define BATCHES    8
#define OUT_PER_B  1792

// K2 geometry
#define K2_TOK     64
#define K2_BLOCKS  (NTOK_TOTAL / K2_TOK)      // 256
#define BLK_PER_B  (K2_BLOCKS / BATCHES)      // 32
#define NCH        128                        // neurons per chunk
#define EPH        514                        // Ebuf pitch in fp32 (even: 8B align)

// K2 dynamic smem (bytes)
#define OFF_B2H    0                          // 128 x 128B
#define OFF_B2L    16384
#define OFF_E2     32768                      // 64 x 514 x 4B = 131584
#define OFF_Z2     164352                     // 128 floats
#define OFF_C2     164864                     // 64 floats
#define K2_SMEM    165120

// K1 dynamic smem (bytes)
#define K1_XH      0                          // 128 x 128B
#define K1_XL      16384
#define K1_WH      32768                      // 64 x 128B
#define K1_WL      40960
#define K1_SMEM    49152

#define SWZ(r, b)  (((unsigned)(r) << 7) + ((unsigned)(b) ^ ((((unsigned)(r)) & 7u) << 4)))

// scratch
__device__ __nv_bfloat16 g_embB_hi[NUSE * DS];
__device__ __nv_bfloat16 g_embB_lo[NUSE * DS];
__device__ __nv_bfloat16 g_WB_hi[DS * DDIM];
__device__ __nv_bfloat16 g_WB_lo[DS * DDIM];
__device__ __nv_bfloat16 g_hB_hi[NTOK_TOTAL * DS];
__device__ __nv_bfloat16 g_hB_lo[NTOK_TOTAL * DS];
__device__ float g_part[K2_BLOCKS * NUSE];
__device__ float g_dense[BATCHES * NUSE];

// ---- helpers --------------------------------------------------------------
__device__ __forceinline__ uint32_t smem_u32(const void* p) {
    uint32_t a;
    asm("{ .reg .u64 t; cvta.to.shared.u64 t, %1; cvt.u32.u64 %0, t; }"
        : "=r"(a) : "l"(p));
    return a;
}

__device__ __forceinline__ void ldsm4(uint32_t& r0, uint32_t& r1,
                                      uint32_t& r2, uint32_t& r3, uint32_t a) {
    asm volatile("ldmatrix.sync.aligned.m8n8.x4.shared.b16 {%0,%1,%2,%3}, [%4];"
                 : "=r"(r0), "=r"(r1), "=r"(r2), "=r"(r3) : "r"(a));
}

__device__ __forceinline__ void mma16816(float* d, const uint32_t* a,
                                         uint32_t b0, uint32_t b1) {
    asm volatile("mma.sync.aligned.m16n8k16.row.col.f32.bf16.bf16.f32 "
                 "{%0,%1,%2,%3}, {%4,%5,%6,%7}, {%8,%9}, {%0,%1,%2,%3};"
                 : "+f"(d[0]), "+f"(d[1]), "+f"(d[2]), "+f"(d[3])
                 : "r"(a[0]), "r"(a[1]), "r"(a[2]), "r"(a[3]), "r"(b0), "r"(b1));
}

__device__ __forceinline__ uint32_t bits2(__nv_bfloat162 v) {
    return *reinterpret_cast<uint32_t*>(&v);
}

// ---------------------------------------------------------------------------
// K0: normalize emb + bf16 split, [n][64]
// ---------------------------------------------------------------------------
__global__ void __launch_bounds__(256) k0_norm(const float* __restrict__ emb) {
    int n = blockIdx.x * 8 + (threadIdx.x >> 5);
    int lane = threadIdx.x & 31;
    if (n >= NUSE) return;
    float v0 = emb[n * DS + lane];
    float v1 = emb[n * DS + 32 + lane];
    float ss = v0 * v0 + v1 * v1;
    #pragma unroll
    for (int o = 16; o; o >>= 1) ss += __shfl_xor_sync(0xFFFFFFFFu, ss, o);
    float inv = 1.0f / sqrtf(ss);
    v0 *= inv; v1 *= inv;
    __nv_bfloat16 h0 = __float2bfloat16(v0);
    __nv_bfloat16 h1 = __float2bfloat16(v1);
    g_embB_hi[n * DS + lane]      = h0;
    g_embB_hi[n * DS + 32 + lane] = h1;
    g_embB_lo[n * DS + lane]      = __float2bfloat16(v0 - __bfloat162float(h0));
    g_embB_lo[n * DS + 32 + lane] = __float2bfloat16(v1 - __bfloat162float(h1));
}

// ---------------------------------------------------------------------------
// K0w: split W
// ---------------------------------------------------------------------------
__global__ void __launch_bounds__(256) k0_w(const float* __restrict__ W) {
    int i = blockIdx.x * 256 + threadIdx.x;
    if (i >= DS * DDIM) return;
    float v = W[i];
    __nv_bfloat16 h = __float2bfloat16(v);
    g_WB_hi[i] = h;
    g_WB_lo[i] = __float2bfloat16(v - __bfloat162float(h));
}

// ---------------------------------------------------------------------------
// K1: h = x @ W^T + b via mma.sync, 128-token CTAs (grid 128), BK=64
// ---------------------------------------------------------------------------
__global__ void __launch_bounds__(256) k1_mma(const float* __restrict__ x,
                                             const float* __restrict__ bias) {
    extern __shared__ __align__(16) char sm1[];
    const int tid = threadIdx.x;
    const int lane = tid & 31;
    const int w = tid >> 5;
    const int wtok = w >> 1;       // 0..3 -> 32 rows each
    const int nhalf = w & 1;       // 0..1 -> 32 cols each
    const int rowBase = blockIdx.x * 128;

    const uint32_t xhB = smem_u32(sm1 + K1_XH), xlB = smem_u32(sm1 + K1_XL);
    const uint32_t whB = smem_u32(sm1 + K1_WH), wlB = smem_u32(sm1 + K1_WL);

    float acc[2][4][4] = {};
    float4 xv[8];
    uint4  wvh[2], wvl[2];

    // prefetch chunk 0
    #pragma unroll
    for (int i = 0; i < 8; i++) {
        int f = tid + i * 256;
        int row = f >> 4, kq = f & 15;
        xv[i] = *(const float4*)(x + (size_t)(rowBase + row) * DDIM + kq * 4);
    }
    #pragma unroll
    for (int i = 0; i < 2; i++) {
        int u = tid + i * 256;
        int row = u >> 3, kq8 = u & 7;
        wvh[i] = *(const uint4*)(g_WB_hi + (size_t)row * DDIM + kq8 * 8);
        wvl[i] = *(const uint4*)(g_WB_lo + (size_t)row * DDIM + kq8 * 8);
    }

    for (int c = 0; c < DDIM / 64; c++) {
        if (c) __syncthreads();
        #pragma unroll
        for (int i = 0; i < 8; i++) {
            int f = tid + i * 256;
            int row = f >> 4, kq = f & 15;
            float4 v = xv[i];
            __nv_bfloat162 h0 = __floats2bfloat162_rn(v.x, v.y);
            __nv_bfloat162 h1 = __floats2bfloat162_rn(v.z, v.w);
            __nv_bfloat162 l0 = __floats2bfloat162_rn(v.x - __bfloat162float(h0.x),
                                                      v.y - __bfloat162float(h0.y));
            __nv_bfloat162 l1 = __floats2bfloat162_rn(v.z - __bfloat162float(h1.x),
                                                      v.w - __bfloat162float(h1.y));
            uint32_t off = SWZ(row, kq * 8);
            *(uint2*)(sm1 + K1_XH + off) = make_uint2(bits2(h0), bits2(h1));
            *(uint2*)(sm1 + K1_XL + off) = make_uint2(bits2(l0), bits2(l1));
        }
        #pragma unroll
        for (int i = 0; i < 2; i++) {
            int u = tid + i * 256;
            int row = u >> 3, kq8 = u & 7;
            uint32_t off = SWZ(row, kq8 * 16);
            *(uint4*)(sm1 + K1_WH + off) = wvh[i];
            *(uint4*)(sm1 + K1_WL + off) = wvl[i];
        }
        __syncthreads();

        if (c + 1 < DDIM / 64) {
            int kk = (c + 1) * 64;
            #pragma unroll
            for (int i = 0; i < 8; i++) {
                int f = tid + i * 256;
                int row = f >> 4, kq = f & 15;
                xv[i] = *(const float4*)(x + (size_t)(rowBase + row) * DDIM + kk + kq * 4);
            }
            #pragma unroll
            for (int i = 0; i < 2; i++) {
                int u = tid + i * 256;
                int row = u >> 3, kq8 = u & 7;
                wvh[i] = *(const uint4*)(g_WB_hi + (size_t)row * DDIM + kk + kq8 * 8);
                wvl[i] = *(const uint4*)(g_WB_lo + (size_t)row * DDIM + kk + kq8 * 8);
            }
        }

        #pragma unroll
        for (int ks = 0; ks < 4; ks++) {
            uint32_t ah[2][4], al[2][4];
            #pragma unroll
            for (int t = 0; t < 2; t++) {
                int R = wtok * 32 + t * 16 + (lane & 15);
                int byte = ks * 32 + (lane >> 4) * 16;
                ldsm4(ah[t][0], ah[t][1], ah[t][2], ah[t][3], xhB + SWZ(R, byte));
                ldsm4(al[t][0], al[t][1], al[t][2], al[t][3], xlB + SWZ(R, byte));
            }
            #pragma unroll
            for (int p = 0; p < 2; p++) {
                int R = nhalf * 32 + (2 * p + (lane >= 16 ? 1 : 0)) * 8 + (lane & 7);
                int byte = ks * 32 + ((lane >> 3) & 1) * 16;
                uint32_t bh0, bh1, bh2, bh3, bl0, bl1, bl2, bl3;
                ldsm4(bh0, bh1, bh2, bh3, whB + SWZ(R, byte));
                ldsm4(bl0, bl1, bl2, bl3, wlB + SWZ(R, byte));
                #pragma unroll
                for (int t = 0; t < 2; t++) {
                    mma16816(acc[t][2 * p],     ah[t], bh0, bh1);
                    mma16816(acc[t][2 * p],     ah[t], bl0, bl1);
                    mma16816(acc[t][2 * p],     al[t], bh0, bh1);
                    mma16816(acc[t][2 * p + 1], ah[t], bh2, bh3);
                    mma16816(acc[t][2 * p + 1], ah[t], bl2, bl3);
                    mma16816(acc[t][2 * p + 1], al[t], bh2, bh3);
                }
            }
        }
    }

    // epilogue
    #pragma unroll
    for (int t = 0; t < 2; t++) {
        #pragma unroll
        for (int n8 = 0; n8 < 4; n8++) {
            int n = nhalf * 32 + n8 * 8 + 2 * (lane & 3);
            int r0 = rowBase + wtok * 32 + t * 16 + (lane >> 2);
            int r1 = r0 + 8;
            float b0 = bias[n], b1 = bias[n + 1];
            float v00 = acc[t][n8][0] + b0, v01 = acc[t][n8][1] + b1;
            float v10 = acc[t][n8][2] + b0, v11 = acc[t][n8][3] + b1;
            __nv_bfloat162 h0 = __floats2bfloat162_rn(v00, v01);
            __nv_bfloat162 h1 = __floats2bfloat162_rn(v10, v11);
            __nv_bfloat162 l0 = __floats2bfloat162_rn(v00 - __bfloat162float(h0.x),
                                                      v01 - __bfloat162float(h0.y));
            __nv_bfloat162 l1 = __floats2bfloat162_rn(v10 - __bfloat162float(h1.x),
                                                      v11 - __bfloat162float(h1.y));
            *(__nv_bfloat162*)(g_hB_hi + (size_t)r0 * DS + n) = h0;
            *(__nv_bfloat162*)(g_hB_hi + (size_t)r1 * DS + n) = h1;
            *(__nv_bfloat162*)(g_hB_lo + (size_t)r0 * DS + n) = l0;
            *(__nv_bfloat162*)(g_hB_lo + (size_t)r1 * DS + n) = l1;
        }
    }
}

// ---------------------------------------------------------------------------
// K2: 64 tokens/CTA, A frags in regs, B staged 128-neuron chunks,
// exp -> fp32 Ebuf (smem) + fp32 Z, per-group coef + column reduce.
// ---------------------------------------------------------------------------
__global__ void __launch_bounds__(256, 1) k2_route(const float* __restrict__ imp) {
    extern __shared__ __align__(16) char sm[];
    const uint32_t base = smem_u32(sm);
    float* Ebuf = (float*)(sm + OFF_E2);
    float* zsm  = (float*)(sm + OFF_Z2);
    float* coef = (float*)(sm + OFF_C2);

    const int tid = threadIdx.x;
    const int lane = tid & 31;
    const int w = tid >> 5;
    const int wtok = w >> 1;      // 0..3 -> 16 token rows
    const int nhalf = w & 1;      // 0..1 -> 64-col half of 128-chunk
    const int bid = blockIdx.x;
    const int tokBase = bid * K2_TOK;

    // A (h) fragments, register-resident for the whole kernel.
    uint32_t ah[4][4], al[4][4];
    {
        const int ra = tokBase + wtok * 16 + (lane >> 2);
        #pragma unroll
        for (int ks = 0; ks < 4; ks++) {
            int kb = ks * 16 + 2 * (lane & 3);
            ah[ks][0] = *(const uint32_t*)(g_hB_hi + (size_t)ra * DS + kb);
            ah[ks][1] = *(const uint32_t*)(g_hB_hi + (size_t)(ra + 8) * DS + kb);
            ah[ks][2] = *(const uint32_t*)(g_hB_hi + (size_t)ra * DS + kb + 8);
            ah[ks][3] = *(const uint32_t*)(g_hB_hi + (size_t)(ra + 8) * DS + kb + 8);
            al[ks][0] = *(const uint32_t*)(g_hB_lo + (size_t)ra * DS + kb);
            al[ks][1] = *(const uint32_t*)(g_hB_lo + (size_t)(ra + 8) * DS + kb);
            al[ks][2] = *(const uint32_t*)(g_hB_lo + (size_t)ra * DS + kb + 8);
            al[ks][3] = *(const uint32_t*)(g_hB_lo + (size_t)(ra + 8) * DS + kb + 8);
        }
    }

    const int gnch[4]  = {4, 4, 2, 2};
    const int gbase[4] = {0, 512, 1024, 1280};
    int chunk = 0;

    for (int grp = 0; grp < 4; grp++) {
        float zr0 = 0.f, zr1 = 0.f;
        for (int ci = 0; ci < gnch[grp]; ci++, chunk++) {
            const int nb = chunk * NCH;
            __syncthreads();   // prev B reads + prev-group Ebuf reads done
            #pragma unroll
            for (int i = 0; i < 4; i++) {          // 128 rows x 8 uint4 = 1024 items
                int v = tid + i * 256;
                int row = v >> 3, kq8 = v & 7;
                uint32_t off = SWZ(row, kq8 * 16);
                *(uint4*)(sm + OFF_B2H + off) =
                    *(const uint4*)(g_embB_hi + (size_t)(nb + row) * DS + kq8 * 8);
                *(uint4*)(sm + OFF_B2L + off) =
                    *(const uint4*)(g_embB_lo + (size_t)(nb + row) * DS + kq8 * 8);
            }
            __syncthreads();

            float acc[8][4];
            #pragma unroll
            for (int i = 0; i < 8; i++) {
                acc[i][0] = 0.f; acc[i][1] = 0.f; acc[i][2] = 0.f; acc[i][3] = 0.f;
            }
            #pragma unroll
            for (int ks = 0; ks < 4; ks++) {
                #pragma unroll
                for (int p = 0; p < 4; p++) {
                    int R = nhalf * 64 + (2 * p + (lane >= 16 ? 1 : 0)) * 8 + (lane & 7);
                    int byte = ks * 32 + ((lane >> 3) & 1) * 16;
                    uint32_t bh0, bh1, bh2, bh3, bl0, bl1, bl2, bl3;
                    ldsm4(bh0, bh1, bh2, bh3, base + OFF_B2H + SWZ(R, byte));
                    ldsm4(bl0, bl1, bl2, bl3, base + OFF_B2L + SWZ(R, byte));
                    mma16816(acc[2 * p],     ah[ks], bh0, bh1);
                    mma16816(acc[2 * p],     ah[ks], bl0, bl1);
                    mma16816(acc[2 * p],     al[ks], bh0, bh1);
                    mma16816(acc[2 * p + 1], ah[ks], bh2, bh3);
                    mma16816(acc[2 * p + 1], ah[ks], bl2, bl3);
                    mma16816(acc[2 * p + 1], al[ks], bh2, bh3);
                }
            }

            // exp -> fp32 Ebuf + fp32 z accumulation
            const int r0 = wtok * 16 + (lane >> 2);
            #pragma unroll
            for (int n8 = 0; n8 < 8; n8++) {
                int colg = ci * NCH + nhalf * 64 + n8 * 8 + 2 * (lane & 3);
                float e00 = __expf(acc[n8][0]);
                float e01 = __expf(acc[n8][1]);
                float e10 = __expf(acc[n8][2]);
                float e11 = __expf(acc[n8][3]);
                *(float2*)(Ebuf + (size_t)r0 * EPH + colg)       = make_float2(e00, e01);
                *(float2*)(Ebuf + (size_t)(r0 + 8) * EPH + colg) = make_float2(e10, e11);
                zr0 += e00 + e01;
                zr1 += e10 + e11;
            }
        }
        // Z: reduce over the 4 lanes sharing a row, then smem
        zr0 += __shfl_xor_sync(0xFFFFFFFFu, zr0, 1);
        zr0 += __shfl_xor_sync(0xFFFFFFFFu, zr0, 2);
        zr1 += __shfl_xor_sync(0xFFFFFFFFu, zr1, 1);
        zr1 += __shfl_xor_sync(0xFFFFFFFFu, zr1, 2);
        {
            const int r0 = wtok * 16 + (lane >> 2);
            if ((lane & 3) == 0) {
                zsm[r0 * 2 + nhalf]       = zr0;
                zsm[(r0 + 8) * 2 + nhalf] = zr1;
            }
        }
        __syncthreads();
        if (tid < K2_TOK)
            coef[tid] = imp[tokBase + tid] / (zsm[2 * tid] + zsm[2 * tid + 1]);
        __syncthreads();

        // column reduce: dense partial over 64 tokens (fp32 pairs)
        {
            const int halfw = (gnch[grp] * NCH) >> 1;
            for (int np = tid; np < halfw; np += 256) {
                const float2* ecol = (const float2*)Ebuf + np;
                float s0 = 0.f, s1 = 0.f;
                #pragma unroll 8
                for (int t = 0; t < K2_TOK; t++) {
                    float2 f = ecol[t * (EPH / 2)];
                    float c = coef[t];
                    s0 += c * f.x;
                    s1 += c * f.y;
                }
                size_t o = (size_t)bid * NUSE + gbase[grp] + 2 * np;
                g_part[o]     = s0;
                g_part[o + 1] = s1;
            }
        }
    }
}

// ---------------------------------------------------------------------------
// K2b: reduce 32 per-tile partials per batch
// ---------------------------------------------------------------------------
__global__ void __launch_bounds__(256) k2b_reduce() {
    int gidx = blockIdx.x * 256 + threadIdx.x;
    if (gidx >= BATCHES * NUSE) return;
    int b = gidx / NUSE, n = gidx - b * NUSE;
    const float* p = g_part + (size_t)b * BLK_PER_B * NUSE + n;
    float sum = 0.f;
    #pragma unroll
    for (int j = 0; j < BLK_PER_B; j++) sum += p[(size_t)j * NUSE];
    g_dense[b * NUSE + n] = sum;
}

// ---------------------------------------------------------------------------
// K3: per (batch,group) top-k + renormalize + scatter (rq duplicated into rk)
// ---------------------------------------------------------------------------
__global__ void __launch_bounds__(256) k3_topk(float* __restrict__ out) {
    const int gs_[4]  = {0, 512, 1024, 1280};
    const int gl_[4]  = {512, 512, 256, 256};
    const int kk_[4]  = {8, 8, 4, 6};
    const int oo_[4]  = {0, 512, 1024, 1536};

    int task = blockIdx.x;
    int b = task >> 2, g = task & 3;
    int len = gl_[g], K = kk_[g];

    __shared__ float sv[512];
    __shared__ float wv[512];
    __shared__ unsigned char sel[512];
    __shared__ float red[8];
    __shared__ int   redi[8];
    __shared__ float s_ksum;

    const float* dn = g_dense + b * NUSE + gs_[g];
    for (int i = threadIdx.x; i < len; i += 256) {
        float v = dn[i];
        sv[i] = v; wv[i] = v; sel[i] = 0;
    }
    if (threadIdx.x == 0) s_ksum = 0.f;
    __syncthreads();

    for (int it = 0; it < K; it++) {
        float best = -1e30f; int bi = 0x7FFFFFFF;
        for (int i = threadIdx.x; i < len; i += 256) {
            float v = wv[i];
            if (v > best || (v == best && i < bi)) { best = v; bi = i; }
        }
        #pragma unroll
        for (int o = 16; o; o >>= 1) {
            float ov = __shfl_xor_sync(0xFFFFFFFFu, best, o);
            int   oi = __shfl_xor_sync(0xFFFFFFFFu, bi,   o);
            if (ov > best || (ov == best && oi < bi)) { best = ov; bi = oi; }
        }
        if ((threadIdx.x & 31) == 0) { red[threadIdx.x >> 5] = best; redi[threadIdx.x >> 5] = bi; }
        __syncthreads();
        if (threadIdx.x == 0) {
            float bb = red[0]; int bbi = redi[0];
            for (int ww = 1; ww < 8; ww++)
                if (red[ww] > bb || (red[ww] == bb && redi[ww] < bbi)) { bb = red[ww]; bbi = redi[ww]; }
            sel[bbi] = 1; wv[bbi] = -1e30f; s_ksum += sv[bbi];
        }
        __syncthreads();
    }

    float inv = 1.0f / (s_ksum + 1e-8f);
    float* ob = out + b * OUT_PER_B;
    for (int i = threadIdx.x; i < len; i += 256) {
        float o = sel[i] ? sv[i] * inv : 0.0f;
        ob[oo_[g] + i] = o;
        if (g == 2) ob[1280 + i] = o;
    }
}

// ---------------------------------------------------------------------------
extern "C" void kernel_launch(void* const* d_in, const int* in_sizes, int n_in,
                              void* d_out, int out_size) {
    const float* x    = (const float*)d_in[0];
    const float* imp  = (const float*)d_in[1];
    const float* W    = (const float*)d_in[2];
    const float* bias = (const float*)d_in[3];
    const float* emb  = (const float*)d_in[4];
    float* out = (float*)d_out;
    (void)in_sizes; (void)n_in; (void)out_size;

    (void)cudaFuncSetAttribute(k1_mma, cudaFuncAttributeMaxDynamicSharedMemorySize,
                               K1_SMEM);
    (void)cudaFuncSetAttribute(k2_route, cudaFuncAttributeMaxDynamicSharedMemorySize,
                               K2_SMEM);

    k0_norm<<<NUSE / 8, 256>>>(emb);
    k0_w<<<(DS * DDIM) / 256, 256>>>(W);
    k1_mma<<<NTOK_TOTAL / 128, 256, K1_SMEM>>>(x, bias);
    k2_route<<<K2_BLOCKS, 256, K2_SMEM>>>(imp);
    k2b_reduce<<<(BATCHES * NUSE + 255) / 256, 256>>>();
    k3_topk<<<BATCHES * 4, 256>>>(out);
}